// round 14
// baseline (speedup 1.0000x reference)
#include <cuda_runtime.h>
#include <cuda_fp16.h>
#include <cstdint>

#define N_HEADS 4
#define NSLOPE 0.2f

#define MAXNX 9000
#define MAXNC 1000
#define MAXN  (MAXNX + MAXNC)
#define MAXE0 40000
#define MAXE  (MAXE0 + MAXN)

// ------------------------- static scratch (no allocs) -------------------------
__device__ __half g_hxin[MAXNX * 400];
__device__ __half g_hxh[MAXNX * 512];
__device__ __half g_hxc[MAXN * 1024];
__device__ __half g_hxlr[(size_t)MAXN * 8192];   // [n, 0:4096)=xl, [4096:8192)=xr
__device__ __half g_houtm[MAXN * 1024];
__device__ __half g_hw1[512 * 400];
__device__ __half g_hw2[1024 * 512];
__device__ __half g_hwlr[(size_t)8192 * 1024];   // Wl^T rows 0-4095, Wr^T rows 4096-8191
__device__ __half g_hwfc[460 * 1024];
__device__ float  g_bcat[8192];
__device__ float  g_alpha[MAXE * N_HEADS];
__device__ int    g_src[MAXE];
__device__ int    g_dst[MAXE];
__device__ int    g_deg[MAXN];
__device__ int    g_off[MAXN + 1];
__device__ int    g_cur[MAXN];
__device__ int    g_csr[MAXE];

// ------------------------- helpers -------------------------
__device__ __forceinline__ void cp16(uint32_t saddr, const void* g, bool valid) {
    int sz = valid ? 16 : 0;   // sz=0 -> 16B zero-fill
    asm volatile("cp.async.cg.shared.global [%0], [%1], 16, %2;\n"
                 :: "r"(saddr), "l"(g), "r"(sz));
}

// ------------------------- small utility kernels -------------------------
__global__ void zero_int2(int* a, int* b, int n) {
    int i = blockIdx.x * blockDim.x + threadIdx.x;
    if (i < n) { a[i] = 0; b[i] = 0; }
}
__global__ void copy_f4(const float4* __restrict__ s, float4* __restrict__ d, int n4) {
    int i = blockIdx.x * blockDim.x + threadIdx.x;
    if (i < n4) d[i] = s[i];
}
__global__ void f2h(const float2* __restrict__ a, __half2* __restrict__ b, int n2) {
    int i = blockIdx.x * blockDim.x + threadIdx.x;
    if (i < n2) b[i] = __float22half2_rn(a[i]);
}
// W [K,N] fp32 row-major -> out [N,K] half (K-major rows)
__global__ void transpose_h(const float* __restrict__ in, __half* __restrict__ out,
                            int K, int N) {
    __shared__ float t[32][33];
    int k0 = blockIdx.x * 32, n0 = blockIdx.y * 32;
    int x = threadIdx.x, y = threadIdx.y;
    #pragma unroll
    for (int j = 0; j < 32; j += 8) {
        int k = k0 + y + j, n = n0 + x;
        t[y + j][x] = (k < K && n < N) ? in[(size_t)k * N + n] : 0.0f;
    }
    __syncthreads();
    #pragma unroll
    for (int j = 0; j < 32; j += 8) {
        int n = n0 + y + j, k = k0 + x;
        if (n < N && k < K) out[(size_t)n * K + k] = __float2half(t[x][y + j]);
    }
}

// edge_index is int32 (JAX x64-disabled downcast)
__global__ void build_edges(const int* __restrict__ ei, int* __restrict__ src,
                            int* __restrict__ dst, int* __restrict__ deg, int E, int N) {
    int e = blockIdx.x * blockDim.x + threadIdx.x;
    int ET = E + N;
    if (e >= ET) return;
    int s, d;
    if (e < E) { s = ei[2 * e]; d = ei[2 * e + 1]; }
    else       { s = d = e - E; }
    src[e] = s; dst[e] = d;
    atomicAdd(&deg[d], 1);
}
__global__ void scan_excl(const int* __restrict__ deg, int* __restrict__ off, int n) {
    __shared__ int sh[1024];
    __shared__ int carry;
    if (threadIdx.x == 0) carry = 0;
    __syncthreads();
    for (int base = 0; base < n; base += 1024) {
        int i = base + threadIdx.x;
        int v = (i < n) ? deg[i] : 0;
        sh[threadIdx.x] = v;
        __syncthreads();
        #pragma unroll
        for (int ofs = 1; ofs < 1024; ofs <<= 1) {
            int t = (threadIdx.x >= ofs) ? sh[threadIdx.x - ofs] : 0;
            __syncthreads();
            sh[threadIdx.x] += t;
            __syncthreads();
        }
        if (i < n) off[i] = carry + sh[threadIdx.x] - v;
        __syncthreads();
        if (threadIdx.x == 1023) carry += sh[1023];
        __syncthreads();
    }
    if (threadIdx.x == 0) off[n] = carry;
}
__global__ void fill_csr(const int* __restrict__ dst, const int* __restrict__ off,
                         int* __restrict__ cur, int* __restrict__ csr, int ET) {
    int e = blockIdx.x * blockDim.x + threadIdx.x;
    if (e >= ET) return;
    int d = dst[e];
    int p = off[d] + atomicAdd(&cur[d], 1);
    csr[p] = e;
}

// ===================== fp16 tensor-core GEMM (m16n8k16 + ldmatrix) =====================
#define BM 128
#define BN 128
#define HBK 64
#define HPAD 72
#define HA_HALVES (BM * HPAD)
#define HB_HALVES (BN * HPAD)
#define HSTG_BYTES ((HA_HALVES + HB_HALVES) * 2)
#define HNST 3
#define H_SMEM (HNST * HSTG_BYTES)

__device__ __forceinline__ void ldm_x4(uint32_t* d, uint32_t addr) {
    asm volatile("ldmatrix.sync.aligned.m8n8.x4.shared.b16 {%0,%1,%2,%3}, [%4];"
                 : "=r"(d[0]), "=r"(d[1]), "=r"(d[2]), "=r"(d[3]) : "r"(addr));
}
__device__ __forceinline__ void mma16816(float* c, const uint32_t* a, uint32_t b0, uint32_t b1) {
    asm volatile(
        "mma.sync.aligned.m16n8k16.row.col.f32.f16.f16.f32 "
        "{%0,%1,%2,%3}, {%4,%5,%6,%7}, {%8,%9}, {%0,%1,%2,%3};\n"
        : "+f"(c[0]), "+f"(c[1]), "+f"(c[2]), "+f"(c[3])
        : "r"(a[0]), "r"(a[1]), "r"(a[2]), "r"(a[3]), "r"(b0), "r"(b1));
}

template <bool RELU, bool HALF_OUT>
__global__ __launch_bounds__(256, 2)
void gemm_h(const __half* __restrict__ A, const __half* __restrict__ Bt,
            const float* __restrict__ bias, void* __restrict__ Cv,
            int M, int N, int K) {
    extern __shared__ char sm[];
    int tid  = threadIdx.x;
    int warp = tid >> 5;
    int lane = tid & 31;
    int g = lane >> 2;
    int t = lane & 3;
    int wm = warp >> 2;
    int wn = warp & 3;
    int mbase = wm * 64;
    int nbase = wn * 32;
    int am0 = blockIdx.y * BM;
    int bn0 = blockIdx.x * BN;
    int NIT = (K + HBK - 1) / HBK;

    float acc[4][4][4];
    #pragma unroll
    for (int i = 0; i < 4; i++)
        #pragma unroll
        for (int j = 0; j < 4; j++)
            #pragma unroll
            for (int k = 0; k < 4; k++) acc[i][j][k] = 0.0f;

    uint32_t smbase = (uint32_t)__cvta_generic_to_shared(sm);

    auto load_stage = [&](int it, int st) {
        int kt = it * HBK;
        uint32_t ab = smbase + (uint32_t)(st * HSTG_BYTES);
        uint32_t bb = ab + HA_HALVES * 2;
        #pragma unroll
        for (int i = 0; i < 4; i++) {
            int idx = tid + i * 256;
            int r = idx >> 3, c = idx & 7;
            int kc = kt + c * 8;
            bool v = (am0 + r < M) && (kc + 8 <= K);
            const __half* gp = A + (size_t)(v ? (am0 + r) : 0) * K + (v ? kc : 0);
            cp16(ab + (uint32_t)(r * 144 + c * 16), gp, v);
        }
        #pragma unroll
        for (int i = 0; i < 4; i++) {
            int idx = tid + i * 256;
            int r = idx >> 3, c = idx & 7;
            int kc = kt + c * 8;
            bool v = (bn0 + r < N) && (kc + 8 <= K);
            const __half* gp = Bt + (size_t)(v ? (bn0 + r) : 0) * K + (v ? kc : 0);
            cp16(bb + (uint32_t)(r * 144 + c * 16), gp, v);
        }
        asm volatile("cp.async.commit_group;\n");
    };

    int a_row = lane & 15;
    int a_k   = (lane & 16) >> 1;
    int b_row = (lane & 7) | ((lane & 16) >> 1);
    int b_k   = lane & 8;

    load_stage(0, 0);
    if (NIT > 1) load_stage(1, 1);

    for (int it = 0; it < NIT; it++) {
        asm volatile("cp.async.wait_group 1;\n");
        __syncthreads();
        if (it + 2 < NIT) load_stage(it + 2, (it + 2) % HNST);

        uint32_t ab = smbase + (uint32_t)((it % HNST) * HSTG_BYTES);
        uint32_t bb = ab + HA_HALVES * 2;

        #pragma unroll
        for (int kk = 0; kk < HBK; kk += 16) {
            uint32_t a[4][4], b[2][4];
            #pragma unroll
            for (int mf = 0; mf < 4; mf++)
                ldm_x4(a[mf], ab + (uint32_t)((mbase + mf * 16 + a_row) * 144 + (kk + a_k) * 2));
            #pragma unroll
            for (int p = 0; p < 2; p++)
                ldm_x4(b[p], bb + (uint32_t)((nbase + p * 16 + b_row) * 144 + (kk + b_k) * 2));
            #pragma unroll
            for (int p = 0; p < 2; p++)
                #pragma unroll
                for (int mf = 0; mf < 4; mf++) {
                    mma16816(acc[mf][2 * p],     a[mf], b[p][0], b[p][1]);
                    mma16816(acc[mf][2 * p + 1], a[mf], b[p][2], b[p][3]);
                }
        }
        __syncthreads();
    }

    #pragma unroll
    for (int mf = 0; mf < 4; mf++) {
        int row0 = am0 + mbase + mf * 16 + g;
        int row1 = row0 + 8;
        #pragma unroll
        for (int nf = 0; nf < 4; nf++) {
            int col = bn0 + nbase + nf * 8 + 2 * t;
            if (col >= N) continue;
            float2 bv = *(const float2*)(bias + col);
            float v0 = acc[mf][nf][0] + bv.x;
            float v1 = acc[mf][nf][1] + bv.y;
            float v2 = acc[mf][nf][2] + bv.x;
            float v3 = acc[mf][nf][3] + bv.y;
            if (RELU) {
                v0 = fmaxf(v0, 0.f); v1 = fmaxf(v1, 0.f);
                v2 = fmaxf(v2, 0.f); v3 = fmaxf(v3, 0.f);
            }
            if (HALF_OUT) {
                __half2* C = (__half2*)Cv;
                if (row0 < M) C[((size_t)row0 * N + col) >> 1] = __floats2half2_rn(v0, v1);
                if (row1 < M) C[((size_t)row1 * N + col) >> 1] = __floats2half2_rn(v2, v3);
            } else {
                float* C = (float*)Cv;
                if (row0 < M) *(float2*)(C + (size_t)row0 * N + col) = make_float2(v0, v1);
                if (row1 < M) *(float2*)(C + (size_t)row1 * N + col) = make_float2(v2, v3);
            }
        }
    }
}

// ------------------------- fused GATv2 (half2-vectorized) -------------------------
// xlr rows: [xl | xr], stride 8192 halves = 4096 half2 slots (xl 0:2048, xr 2048:4096).
__global__ __launch_bounds__(256)
void gat_fused(const __half* __restrict__ xlr,
               const int* __restrict__ off, const int* __restrict__ csr,
               const int* __restrict__ src, const float* __restrict__ att,
               const float* __restrict__ gat_bias, float* __restrict__ alpha_s,
               __half* __restrict__ outm, int N) {
    int n = blockIdx.x;
    if (n >= N) return;
    int t = threadIdx.x;
    int lane = t & 31, wid = t >> 5;
    int b = off[n], e2 = off[n + 1];

    __shared__ float s_xr[4096];
    __shared__ float s_att[4096];
    __shared__ float sm_m[N_HEADS], sm_inv[N_HEADS];

    const __half2* xrp = (const __half2*)(xlr + (size_t)n * 8192 + 4096);
    #pragma unroll
    for (int j = 0; j < 8; j++) {
        int idx = t + j * 256;
        float2 f = __half22float2(xrp[idx]);
        s_xr[2 * idx] = f.x; s_xr[2 * idx + 1] = f.y;
    }
    const float4* atp = (const float4*)att;
    #pragma unroll
    for (int j = 0; j < 4; j++) {
        int idx = t + j * 256;
        ((float4*)s_att)[idx] = atp[idx];
    }
    __syncthreads();

    // ---- pass 1: logits, one warp per edge, half2 loads ----
    for (int i = b + wid; i < e2; i += 8) {
        int s = src[csr[i]];
        const __half2* pl2 = (const __half2*)(xlr + (size_t)s * 8192);
        float part[N_HEADS];
        #pragma unroll
        for (int h = 0; h < N_HEADS; h++) {
            float p = 0.0f;
            int base2 = h * 512;
            #pragma unroll 4
            for (int k = 0; k < 16; k++) {
                int c2 = base2 + lane + k * 32;
                float2 f = __half22float2(pl2[c2]);
                float v0 = f.x + s_xr[2 * c2];
                float v1 = f.y + s_xr[2 * c2 + 1];
                v0 = (v0 > 0.0f) ? v0 : NSLOPE * v0;
                v1 = (v1 > 0.0f) ? v1 : NSLOPE * v1;
                p += v0 * s_att[2 * c2] + v1 * s_att[2 * c2 + 1];
            }
            part[h] = p;
        }
        #pragma unroll
        for (int h = 0; h < N_HEADS; h++) {
            float v = part[h];
            #pragma unroll
            for (int o = 16; o; o >>= 1) v += __shfl_xor_sync(0xffffffffu, v, o);
            if (lane == 0) alpha_s[(size_t)i * N_HEADS + h] = v;
        }
    }
    __syncthreads();

    if (t < N_HEADS) {
        float m = -1e30f;
        for (int i = b; i < e2; i++)
            m = fmaxf(m, alpha_s[(size_t)i * N_HEADS + t]);
        float z = 0.0f;
        for (int i = b; i < e2; i++)
            z += __expf(alpha_s[(size_t)i * N_HEADS + t] - m);
        sm_m[t] = m;
        sm_inv[t] = 1.0f / (z + 1e-16f);
    }
    __syncthreads();
    float mf0 = sm_m[0], mf1 = sm_m[1], mf2 = sm_m[2], mf3 = sm_m[3];
    float iv0 = sm_inv[0], iv1 = sm_inv[1], iv2 = sm_inv[2], iv3 = sm_inv[3];

    // ---- pass 2: weighted aggregation, half2 loads ----
    // 512 half2 slots per head; thread t owns slots t and t+256 of each head.
    float2 acc[8];
    #pragma unroll
    for (int j = 0; j < 8; j++) acc[j] = make_float2(0.f, 0.f);

    for (int i = b; i < e2; i++) {
        int s = src[csr[i]];
        const __half2* pl2 = (const __half2*)(xlr + (size_t)s * 8192);
        const float* ap = alpha_s + (size_t)i * N_HEADS;
        float w[N_HEADS];
        w[0] = __expf(ap[0] - mf0) * iv0;
        w[1] = __expf(ap[1] - mf1) * iv1;
        w[2] = __expf(ap[2] - mf2) * iv2;
        w[3] = __expf(ap[3] - mf3) * iv3;
        #pragma unroll
        for (int h = 0; h < N_HEADS; h++) {
            #pragma unroll
            for (int j = 0; j < 2; j++) {
                int slot = h * 512 + t + j * 256;
                float2 f = __half22float2(pl2[slot]);
                acc[h * 2 + j].x += w[h] * f.x;
                acc[h * 2 + j].y += w[h] * f.y;
            }
        }
    }

    // head mean + bias; output half2 slots t and t+256 (channels 2slot, 2slot+1)
    #pragma unroll
    for (int j = 0; j < 2; j++) {
        int slot = t + j * 256;
        float2 v;
        v.x = 0.25f * (acc[j].x + acc[2 + j].x + acc[4 + j].x + acc[6 + j].x);
        v.y = 0.25f * (acc[j].y + acc[2 + j].y + acc[4 + j].y + acc[6 + j].y);
        float2 bv = *(const float2*)(gat_bias + 2 * slot);
        ((__half2*)(outm + (size_t)n * 1024))[slot] =
            __floats2half2_rn(v.x + bv.x, v.y + bv.y);
    }
}

// ------------------------- host orchestration -------------------------
static inline dim3 gemm_grid(int M, int N) {
    return dim3((N + BN - 1) / BN, (M + BM - 1) / BM);
}

extern "C" void kernel_launch(void* const* d_in, const int* in_sizes, int n_in,
                              void* d_out, int out_size) {
    const float* x    = (const float*)d_in[0];
    const float* emb  = (const float*)d_in[1];
    const int*   ei   = (const int*)d_in[2];
    const float* exps = (const float*)d_in[3];
    const float* W1   = (const float*)d_in[4];
    const float* b1   = (const float*)d_in[5];
    const float* W2   = (const float*)d_in[6];
    const float* b2   = (const float*)d_in[7];
    const float* Wl   = (const float*)d_in[8];
    const float* bl   = (const float*)d_in[9];
    const float* Wr   = (const float*)d_in[10];
    const float* br   = (const float*)d_in[11];
    const float* att  = (const float*)d_in[12];
    const float* gb   = (const float*)d_in[13];
    const float* Wfc  = (const float*)d_in[14];
    const float* bfc  = (const float*)d_in[15];

    int Nx = in_sizes[0] / 400;
    int Nc = in_sizes[1] / 1024;
    int E  = in_sizes[2] / 2;
    int N  = Nx + Nc;
    int ET = E + N;

    __half *hxin, *hxh, *hxc, *hxlr, *houtm, *hw1, *hw2, *hwlr, *hwfc;
    float *alpha, *bcat;
    int *src, *dst, *deg, *off, *cur, *csr;
    cudaGetSymbolAddress((void**)&hxin,  g_hxin);
    cudaGetSymbolAddress((void**)&hxh,   g_hxh);
    cudaGetSymbolAddress((void**)&hxc,   g_hxc);
    cudaGetSymbolAddress((void**)&hxlr,  g_hxlr);
    cudaGetSymbolAddress((void**)&houtm, g_houtm);
    cudaGetSymbolAddress((void**)&hw1,   g_hw1);
    cudaGetSymbolAddress((void**)&hw2,   g_hw2);
    cudaGetSymbolAddress((void**)&hwlr,  g_hwlr);
    cudaGetSymbolAddress((void**)&hwfc,  g_hwfc);
    cudaGetSymbolAddress((void**)&bcat,  g_bcat);
    cudaGetSymbolAddress((void**)&alpha, g_alpha);
    cudaGetSymbolAddress((void**)&src,   g_src);
    cudaGetSymbolAddress((void**)&dst,   g_dst);
    cudaGetSymbolAddress((void**)&deg,   g_deg);
    cudaGetSymbolAddress((void**)&off,   g_off);
    cudaGetSymbolAddress((void**)&cur,   g_cur);
    cudaGetSymbolAddress((void**)&csr,   g_csr);

    cudaFuncSetAttribute(gemm_h<true,  true >, cudaFuncAttributeMaxDynamicSharedMemorySize, H_SMEM);
    cudaFuncSetAttribute(gemm_h<false, true >, cudaFuncAttributeMaxDynamicSharedMemorySize, H_SMEM);
    cudaFuncSetAttribute(gemm_h<false, false>, cudaFuncAttributeMaxDynamicSharedMemorySize, H_SMEM);

    dim3 tb(32, 8);
    cudaStream_t s0 = 0, s1, s2;
    cudaStreamCreate(&s1);
    cudaStreamCreate(&s2);
    cudaEvent_t eFork, eW1, eW2, eWlr, eWfc, eGraph;
    cudaEventCreateWithFlags(&eFork, cudaEventDisableTiming);
    cudaEventCreateWithFlags(&eW1,   cudaEventDisableTiming);
    cudaEventCreateWithFlags(&eW2,   cudaEventDisableTiming);
    cudaEventCreateWithFlags(&eWlr,  cudaEventDisableTiming);
    cudaEventCreateWithFlags(&eWfc,  cudaEventDisableTiming);
    cudaEventCreateWithFlags(&eGraph,cudaEventDisableTiming);

    // ---- fork side streams ----
    cudaEventRecord(eFork, s0);
    cudaStreamWaitEvent(s1, eFork, 0);
    cudaStreamWaitEvent(s2, eFork, 0);

    // ---- s1: weight prep (overlaps main-chain GEMMs) ----
    transpose_h<<<dim3(13, 16), tb, 0, s1>>>(W1, hw1, 400, 512);
    cudaEventRecord(eW1, s1);
    transpose_h<<<dim3(16, 32), tb, 0, s1>>>(W2, hw2, 512, 1024);
    cudaEventRecord(eW2, s1);
    transpose_h<<<dim3(32, 128), tb, 0, s1>>>(Wl, hwlr, 1024, 4096);
    transpose_h<<<dim3(32, 128), tb, 0, s1>>>(Wr, hwlr + (size_t)4096 * 1024, 1024, 4096);
    copy_f4<<<4, 256, 0, s1>>>((const float4*)bl, (float4*)bcat, 1024);
    copy_f4<<<4, 256, 0, s1>>>((const float4*)br, (float4*)(bcat + 4096), 1024);
    cudaEventRecord(eWlr, s1);
    transpose_h<<<dim3(32, 15), tb, 0, s1>>>(Wfc, hwfc, 1024, 460);
    cudaEventRecord(eWfc, s1);

    // ---- s2: graph structure + exps passthrough (all off critical path) ----
    zero_int2<<<(N + 255) / 256, 256, 0, s2>>>(deg, cur, N);
    build_edges<<<(ET + 255) / 256, 256, 0, s2>>>(ei, src, dst, deg, E, N);
    scan_excl<<<1, 1024, 0, s2>>>(deg, off, N);
    fill_csr<<<(ET + 255) / 256, 256, 0, s2>>>(dst, off, cur, csr, ET);
    copy_f4<<<(Nx * 115 + 255) / 256, 256, 0, s2>>>((const float4*)exps,
                                                    (float4*)((float*)d_out + (size_t)N * 460),
                                                    Nx * 115);
    cudaEventRecord(eGraph, s2);

    // ---- s0: main chain ----
    f2h<<<(Nx * 200 + 255) / 256, 256, 0, s0>>>((const float2*)x, (__half2*)hxin, Nx * 200);
    f2h<<<(Nc * 512 + 255) / 256, 256, 0, s0>>>((const float2*)emb, (__half2*)hxc, Nc * 512);

    cudaStreamWaitEvent(s0, eW1, 0);
    gemm_h<true, true><<<gemm_grid(Nx, 512), 256, H_SMEM, s0>>>(hxin, hw1, b1, hxh, Nx, 512, 400);

    cudaStreamWaitEvent(s0, eW2, 0);
    gemm_h<false, true><<<gemm_grid(Nx, 1024), 256, H_SMEM, s0>>>(hxh, hw2, b2, hxc + (size_t)Nc * 1024, Nx, 1024, 512);

    cudaStreamWaitEvent(s0, eWlr, 0);
    gemm_h<false, true><<<gemm_grid(N, 8192), 256, H_SMEM, s0>>>(hxc, hwlr, bcat, hxlr, N, 8192, 1024);

    cudaStreamWaitEvent(s0, eGraph, 0);
    gat_fused<<<N, 256, 0, s0>>>(hxlr, off, csr, src, att, gb, alpha, houtm, N);

    cudaStreamWaitEvent(s0, eWfc, 0);
    gemm_h<false, false><<<gemm_grid(N, 460), 256, H_SMEM, s0>>>(houtm, hwfc, bfc, (float*)d_out, N, 460, 1024);

    // forks joined into s0 via eWfc (covers all of s1) and eGraph (all of s2)
    cudaEventDestroy(eFork);
    cudaEventDestroy(eW1);
    cudaEventDestroy(eW2);
    cudaEventDestroy(eWlr);
    cudaEventDestroy(eWfc);
    cudaEventDestroy(eGraph);
    cudaStreamDestroy(s1);
    cudaStreamDestroy(s2);
}

// round 15
// speedup vs baseline: 1.0021x; 1.0021x over previous
#include <cuda_runtime.h>
#include <cuda_fp16.h>
#include <cstdint>

#define N_HEADS 4
#define NSLOPE 0.2f

#define MAXNX 9000
#define MAXNC 1000
#define MAXN  (MAXNX + MAXNC)
#define MAXE0 40000
#define MAXE  (MAXE0 + MAXN)

// ------------------------- static scratch (no allocs) -------------------------
__device__ __half g_hxin[MAXNX * 400];
__device__ __half g_hxh[MAXNX * 512];
__device__ __half g_hxc[MAXN * 1024];
__device__ __half g_hxlr[(size_t)MAXN * 8192];   // [n, 0:4096)=xl, [4096:8192)=xr
__device__ __half g_houtm[MAXN * 1024];
__device__ __half g_hw1[512 * 400];
__device__ __half g_hw2[1024 * 512];
__device__ __half g_hwlr[(size_t)8192 * 1024];   // Wl^T rows 0-4095, Wr^T rows 4096-8191
__device__ __half g_hwfc[460 * 1024];
__device__ float  g_bcat[8192];
__device__ float  g_alpha[MAXE * N_HEADS];
__device__ int    g_src[MAXE];
__device__ int    g_dst[MAXE];
__device__ int    g_deg[MAXN];
__device__ int    g_off[MAXN + 1];
__device__ int    g_cur[MAXN];
__device__ int    g_csr[MAXE];

// ------------------------- helpers -------------------------
__device__ __forceinline__ void cp16(uint32_t saddr, const void* g, bool valid) {
    int sz = valid ? 16 : 0;   // sz=0 -> 16B zero-fill
    asm volatile("cp.async.cg.shared.global [%0], [%1], 16, %2;\n"
                 :: "r"(saddr), "l"(g), "r"(sz));
}

// ------------------------- small utility kernels -------------------------
__global__ void zero_int2(int* a, int* b, int n) {
    int i = blockIdx.x * blockDim.x + threadIdx.x;
    if (i < n) { a[i] = 0; b[i] = 0; }
}
__global__ void copy_f4(const float4* __restrict__ s, float4* __restrict__ d, int n4) {
    int i = blockIdx.x * blockDim.x + threadIdx.x;
    if (i < n4) d[i] = s[i];
}
__global__ void f2h(const float2* __restrict__ a, __half2* __restrict__ b, int n2) {
    int i = blockIdx.x * blockDim.x + threadIdx.x;
    if (i < n2) b[i] = __float22half2_rn(a[i]);
}
// W [K,N] fp32 row-major -> out [N,K] half (K-major rows)
__global__ void transpose_h(const float* __restrict__ in, __half* __restrict__ out,
                            int K, int N) {
    __shared__ float t[32][33];
    int k0 = blockIdx.x * 32, n0 = blockIdx.y * 32;
    int x = threadIdx.x, y = threadIdx.y;
    #pragma unroll
    for (int j = 0; j < 32; j += 8) {
        int k = k0 + y + j, n = n0 + x;
        t[y + j][x] = (k < K && n < N) ? in[(size_t)k * N + n] : 0.0f;
    }
    __syncthreads();
    #pragma unroll
    for (int j = 0; j < 32; j += 8) {
        int n = n0 + y + j, k = k0 + x;
        if (n < N && k < K) out[(size_t)n * K + k] = __float2half(t[x][y + j]);
    }
}

// edge_index is int32 (JAX x64-disabled downcast)
__global__ void build_edges(const int* __restrict__ ei, int* __restrict__ src,
                            int* __restrict__ dst, int* __restrict__ deg, int E, int N) {
    int e = blockIdx.x * blockDim.x + threadIdx.x;
    int ET = E + N;
    if (e >= ET) return;
    int s, d;
    if (e < E) { s = ei[2 * e]; d = ei[2 * e + 1]; }
    else       { s = d = e - E; }
    src[e] = s; dst[e] = d;
    atomicAdd(&deg[d], 1);
}
__global__ void scan_excl(const int* __restrict__ deg, int* __restrict__ off, int n) {
    __shared__ int sh[1024];
    __shared__ int carry;
    if (threadIdx.x == 0) carry = 0;
    __syncthreads();
    for (int base = 0; base < n; base += 1024) {
        int i = base + threadIdx.x;
        int v = (i < n) ? deg[i] : 0;
        sh[threadIdx.x] = v;
        __syncthreads();
        #pragma unroll
        for (int ofs = 1; ofs < 1024; ofs <<= 1) {
            int t = (threadIdx.x >= ofs) ? sh[threadIdx.x - ofs] : 0;
            __syncthreads();
            sh[threadIdx.x] += t;
            __syncthreads();
        }
        if (i < n) off[i] = carry + sh[threadIdx.x] - v;
        __syncthreads();
        if (threadIdx.x == 1023) carry += sh[1023];
        __syncthreads();
    }
    if (threadIdx.x == 0) off[n] = carry;
}
__global__ void fill_csr(const int* __restrict__ dst, const int* __restrict__ off,
                         int* __restrict__ cur, int* __restrict__ csr, int ET) {
    int e = blockIdx.x * blockDim.x + threadIdx.x;
    if (e >= ET) return;
    int d = dst[e];
    int p = off[d] + atomicAdd(&cur[d], 1);
    csr[p] = e;
}

// ===================== fp16 tensor-core GEMM (m16n8k16 + ldmatrix) =====================
#define BM 128
#define BN 128
#define HBK 64
#define HPAD 72
#define HA_HALVES (BM * HPAD)
#define HB_HALVES (BN * HPAD)
#define HSTG_BYTES ((HA_HALVES + HB_HALVES) * 2)
#define HNST 3
#define H_SMEM (HNST * HSTG_BYTES)

__device__ __forceinline__ void ldm_x4(uint32_t* d, uint32_t addr) {
    asm volatile("ldmatrix.sync.aligned.m8n8.x4.shared.b16 {%0,%1,%2,%3}, [%4];"
                 : "=r"(d[0]), "=r"(d[1]), "=r"(d[2]), "=r"(d[3]) : "r"(addr));
}
__device__ __forceinline__ void mma16816(float* c, const uint32_t* a, uint32_t b0, uint32_t b1) {
    asm volatile(
        "mma.sync.aligned.m16n8k16.row.col.f32.f16.f16.f32 "
        "{%0,%1,%2,%3}, {%4,%5,%6,%7}, {%8,%9}, {%0,%1,%2,%3};\n"
        : "+f"(c[0]), "+f"(c[1]), "+f"(c[2]), "+f"(c[3])
        : "r"(a[0]), "r"(a[1]), "r"(a[2]), "r"(a[3]), "r"(b0), "r"(b1));
}

template <bool RELU, bool HALF_OUT>
__global__ __launch_bounds__(256, 2)
void gemm_h(const __half* __restrict__ A, const __half* __restrict__ Bt,
            const float* __restrict__ bias, void* __restrict__ Cv,
            int M, int N, int K) {
    extern __shared__ char sm[];
    int tid  = threadIdx.x;
    int warp = tid >> 5;
    int lane = tid & 31;
    int g = lane >> 2;
    int t = lane & 3;
    int wm = warp >> 2;
    int wn = warp & 3;
    int mbase = wm * 64;
    int nbase = wn * 32;
    int am0 = blockIdx.y * BM;
    int bn0 = blockIdx.x * BN;
    int NIT = (K + HBK - 1) / HBK;

    float acc[4][4][4];
    #pragma unroll
    for (int i = 0; i < 4; i++)
        #pragma unroll
        for (int j = 0; j < 4; j++)
            #pragma unroll
            for (int k = 0; k < 4; k++) acc[i][j][k] = 0.0f;

    uint32_t smbase = (uint32_t)__cvta_generic_to_shared(sm);

    auto load_stage = [&](int it, int st) {
        int kt = it * HBK;
        uint32_t ab = smbase + (uint32_t)(st * HSTG_BYTES);
        uint32_t bb = ab + HA_HALVES * 2;
        #pragma unroll
        for (int i = 0; i < 4; i++) {
            int idx = tid + i * 256;
            int r = idx >> 3, c = idx & 7;
            int kc = kt + c * 8;
            bool v = (am0 + r < M) && (kc + 8 <= K);
            const __half* gp = A + (size_t)(v ? (am0 + r) : 0) * K + (v ? kc : 0);
            cp16(ab + (uint32_t)(r * 144 + c * 16), gp, v);
        }
        #pragma unroll
        for (int i = 0; i < 4; i++) {
            int idx = tid + i * 256;
            int r = idx >> 3, c = idx & 7;
            int kc = kt + c * 8;
            bool v = (bn0 + r < N) && (kc + 8 <= K);
            const __half* gp = Bt + (size_t)(v ? (bn0 + r) : 0) * K + (v ? kc : 0);
            cp16(bb + (uint32_t)(r * 144 + c * 16), gp, v);
        }
        asm volatile("cp.async.commit_group;\n");
    };

    int a_row = lane & 15;
    int a_k   = (lane & 16) >> 1;
    int b_row = (lane & 7) | ((lane & 16) >> 1);
    int b_k   = lane & 8;

    load_stage(0, 0);
    if (NIT > 1) load_stage(1, 1);

    for (int it = 0; it < NIT; it++) {
        asm volatile("cp.async.wait_group 1;\n");
        __syncthreads();
        if (it + 2 < NIT) load_stage(it + 2, (it + 2) % HNST);

        uint32_t ab = smbase + (uint32_t)((it % HNST) * HSTG_BYTES);
        uint32_t bb = ab + HA_HALVES * 2;

        #pragma unroll
        for (int kk = 0; kk < HBK; kk += 16) {
            uint32_t a[4][4], b[2][4];
            #pragma unroll
            for (int mf = 0; mf < 4; mf++)
                ldm_x4(a[mf], ab + (uint32_t)((mbase + mf * 16 + a_row) * 144 + (kk + a_k) * 2));
            #pragma unroll
            for (int p = 0; p < 2; p++)
                ldm_x4(b[p], bb + (uint32_t)((nbase + p * 16 + b_row) * 144 + (kk + b_k) * 2));
            #pragma unroll
            for (int p = 0; p < 2; p++)
                #pragma unroll
                for (int mf = 0; mf < 4; mf++) {
                    mma16816(acc[mf][2 * p],     a[mf], b[p][0], b[p][1]);
                    mma16816(acc[mf][2 * p + 1], a[mf], b[p][2], b[p][3]);
                }
        }
        __syncthreads();
    }

    #pragma unroll
    for (int mf = 0; mf < 4; mf++) {
        int row0 = am0 + mbase + mf * 16 + g;
        int row1 = row0 + 8;
        #pragma unroll
        for (int nf = 0; nf < 4; nf++) {
            int col = bn0 + nbase + nf * 8 + 2 * t;
            if (col >= N) continue;
            float2 bv = *(const float2*)(bias + col);
            float v0 = acc[mf][nf][0] + bv.x;
            float v1 = acc[mf][nf][1] + bv.y;
            float v2 = acc[mf][nf][2] + bv.x;
            float v3 = acc[mf][nf][3] + bv.y;
            if (RELU) {
                v0 = fmaxf(v0, 0.f); v1 = fmaxf(v1, 0.f);
                v2 = fmaxf(v2, 0.f); v3 = fmaxf(v3, 0.f);
            }
            if (HALF_OUT) {
                __half2* C = (__half2*)Cv;
                if (row0 < M) C[((size_t)row0 * N + col) >> 1] = __floats2half2_rn(v0, v1);
                if (row1 < M) C[((size_t)row1 * N + col) >> 1] = __floats2half2_rn(v2, v3);
            } else {
                float* C = (float*)Cv;
                if (row0 < M) *(float2*)(C + (size_t)row0 * N + col) = make_float2(v0, v1);
                if (row1 < M) *(float2*)(C + (size_t)row1 * N + col) = make_float2(v2, v3);
            }
        }
    }
}

// ------------------------- fused GATv2 (half2-vectorized) -------------------------
// xlr rows: [xl | xr], stride 8192 halves = 4096 half2 slots (xl 0:2048, xr 2048:4096).
__global__ __launch_bounds__(256)
void gat_fused(const __half* __restrict__ xlr,
               const int* __restrict__ off, const int* __restrict__ csr,
               const int* __restrict__ src, const float* __restrict__ att,
               const float* __restrict__ gat_bias, float* __restrict__ alpha_s,
               __half* __restrict__ outm, int N) {
    int n = blockIdx.x;
    if (n >= N) return;
    int t = threadIdx.x;
    int lane = t & 31, wid = t >> 5;
    int b = off[n], e2 = off[n + 1];

    __shared__ float s_xr[4096];
    __shared__ float s_att[4096];
    __shared__ float sm_m[N_HEADS], sm_inv[N_HEADS];

    const __half2* xrp = (const __half2*)(xlr + (size_t)n * 8192 + 4096);
    #pragma unroll
    for (int j = 0; j < 8; j++) {
        int idx = t + j * 256;
        float2 f = __half22float2(xrp[idx]);
        s_xr[2 * idx] = f.x; s_xr[2 * idx + 1] = f.y;
    }
    const float4* atp = (const float4*)att;
    #pragma unroll
    for (int j = 0; j < 4; j++) {
        int idx = t + j * 256;
        ((float4*)s_att)[idx] = atp[idx];
    }
    __syncthreads();

    // ---- pass 1: logits, one warp per edge, half2 loads ----
    for (int i = b + wid; i < e2; i += 8) {
        int s = src[csr[i]];
        const __half2* pl2 = (const __half2*)(xlr + (size_t)s * 8192);
        float part[N_HEADS];
        #pragma unroll
        for (int h = 0; h < N_HEADS; h++) {
            float p = 0.0f;
            int base2 = h * 512;
            #pragma unroll 4
            for (int k = 0; k < 16; k++) {
                int c2 = base2 + lane + k * 32;
                float2 f = __half22float2(pl2[c2]);
                float v0 = f.x + s_xr[2 * c2];
                float v1 = f.y + s_xr[2 * c2 + 1];
                v0 = (v0 > 0.0f) ? v0 : NSLOPE * v0;
                v1 = (v1 > 0.0f) ? v1 : NSLOPE * v1;
                p += v0 * s_att[2 * c2] + v1 * s_att[2 * c2 + 1];
            }
            part[h] = p;
        }
        #pragma unroll
        for (int h = 0; h < N_HEADS; h++) {
            float v = part[h];
            #pragma unroll
            for (int o = 16; o; o >>= 1) v += __shfl_xor_sync(0xffffffffu, v, o);
            if (lane == 0) alpha_s[(size_t)i * N_HEADS + h] = v;
        }
    }
    __syncthreads();

    if (t < N_HEADS) {
        float m = -1e30f;
        for (int i = b; i < e2; i++)
            m = fmaxf(m, alpha_s[(size_t)i * N_HEADS + t]);
        float z = 0.0f;
        for (int i = b; i < e2; i++)
            z += __expf(alpha_s[(size_t)i * N_HEADS + t] - m);
        sm_m[t] = m;
        sm_inv[t] = 1.0f / (z + 1e-16f);
    }
    __syncthreads();
    float mf0 = sm_m[0], mf1 = sm_m[1], mf2 = sm_m[2], mf3 = sm_m[3];
    float iv0 = sm_inv[0], iv1 = sm_inv[1], iv2 = sm_inv[2], iv3 = sm_inv[3];

    // ---- pass 2: weighted aggregation, half2 loads ----
    float2 acc[8];
    #pragma unroll
    for (int j = 0; j < 8; j++) acc[j] = make_float2(0.f, 0.f);

    for (int i = b; i < e2; i++) {
        int s = src[csr[i]];
        const __half2* pl2 = (const __half2*)(xlr + (size_t)s * 8192);
        const float* ap = alpha_s + (size_t)i * N_HEADS;
        float w[N_HEADS];
        w[0] = __expf(ap[0] - mf0) * iv0;
        w[1] = __expf(ap[1] - mf1) * iv1;
        w[2] = __expf(ap[2] - mf2) * iv2;
        w[3] = __expf(ap[3] - mf3) * iv3;
        #pragma unroll
        for (int h = 0; h < N_HEADS; h++) {
            #pragma unroll
            for (int j = 0; j < 2; j++) {
                int slot = h * 512 + t + j * 256;
                float2 f = __half22float2(pl2[slot]);
                acc[h * 2 + j].x += w[h] * f.x;
                acc[h * 2 + j].y += w[h] * f.y;
            }
        }
    }

    #pragma unroll
    for (int j = 0; j < 2; j++) {
        int slot = t + j * 256;
        float2 v;
        v.x = 0.25f * (acc[j].x + acc[2 + j].x + acc[4 + j].x + acc[6 + j].x);
        v.y = 0.25f * (acc[j].y + acc[2 + j].y + acc[4 + j].y + acc[6 + j].y);
        float2 bv = *(const float2*)(gat_bias + 2 * slot);
        ((__half2*)(outm + (size_t)n * 1024))[slot] =
            __floats2half2_rn(v.x + bv.x, v.y + bv.y);
    }
}

// ------------------------- host orchestration -------------------------
static inline dim3 gemm_grid(int M, int N) {
    return dim3((N + BN - 1) / BN, (M + BM - 1) / BM);
}

extern "C" void kernel_launch(void* const* d_in, const int* in_sizes, int n_in,
                              void* d_out, int out_size) {
    const float* x    = (const float*)d_in[0];
    const float* emb  = (const float*)d_in[1];
    const int*   ei   = (const int*)d_in[2];
    const float* exps = (const float*)d_in[3];
    const float* W1   = (const float*)d_in[4];
    const float* b1   = (const float*)d_in[5];
    const float* W2   = (const float*)d_in[6];
    const float* b2   = (const float*)d_in[7];
    const float* Wl   = (const float*)d_in[8];
    const float* bl   = (const float*)d_in[9];
    const float* Wr   = (const float*)d_in[10];
    const float* br   = (const float*)d_in[11];
    const float* att  = (const float*)d_in[12];
    const float* gb   = (const float*)d_in[13];
    const float* Wfc  = (const float*)d_in[14];
    const float* bfc  = (const float*)d_in[15];

    int Nx = in_sizes[0] / 400;
    int Nc = in_sizes[1] / 1024;
    int E  = in_sizes[2] / 2;
    int N  = Nx + Nc;
    int ET = E + N;

    __half *hxin, *hxh, *hxc, *hxlr, *houtm, *hw1, *hw2, *hwlr, *hwfc;
    float *alpha, *bcat;
    int *src, *dst, *deg, *off, *cur, *csr;
    cudaGetSymbolAddress((void**)&hxin,  g_hxin);
    cudaGetSymbolAddress((void**)&hxh,   g_hxh);
    cudaGetSymbolAddress((void**)&hxc,   g_hxc);
    cudaGetSymbolAddress((void**)&hxlr,  g_hxlr);
    cudaGetSymbolAddress((void**)&houtm, g_houtm);
    cudaGetSymbolAddress((void**)&hw1,   g_hw1);
    cudaGetSymbolAddress((void**)&hw2,   g_hw2);
    cudaGetSymbolAddress((void**)&hwlr,  g_hwlr);
    cudaGetSymbolAddress((void**)&hwfc,  g_hwfc);
    cudaGetSymbolAddress((void**)&bcat,  g_bcat);
    cudaGetSymbolAddress((void**)&alpha, g_alpha);
    cudaGetSymbolAddress((void**)&src,   g_src);
    cudaGetSymbolAddress((void**)&dst,   g_dst);
    cudaGetSymbolAddress((void**)&deg,   g_deg);
    cudaGetSymbolAddress((void**)&off,   g_off);
    cudaGetSymbolAddress((void**)&cur,   g_cur);
    cudaGetSymbolAddress((void**)&csr,   g_csr);

    cudaFuncSetAttribute(gemm_h<true,  true >, cudaFuncAttributeMaxDynamicSharedMemorySize, H_SMEM);
    cudaFuncSetAttribute(gemm_h<false, true >, cudaFuncAttributeMaxDynamicSharedMemorySize, H_SMEM);
    cudaFuncSetAttribute(gemm_h<false, false>, cudaFuncAttributeMaxDynamicSharedMemorySize, H_SMEM);

    dim3 tb(32, 8);
    cudaStream_t s0 = 0, s1, s2;
    cudaStreamCreate(&s1);
    cudaStreamCreate(&s2);
    cudaEvent_t eFork, eW1, eW2, eWlr, eWfc, eGraph;
    cudaEventCreateWithFlags(&eFork, cudaEventDisableTiming);
    cudaEventCreateWithFlags(&eW1,   cudaEventDisableTiming);
    cudaEventCreateWithFlags(&eW2,   cudaEventDisableTiming);
    cudaEventCreateWithFlags(&eWlr,  cudaEventDisableTiming);
    cudaEventCreateWithFlags(&eWfc,  cudaEventDisableTiming);
    cudaEventCreateWithFlags(&eGraph,cudaEventDisableTiming);

    // ---- fork side streams ----
    cudaEventRecord(eFork, s0);
    cudaStreamWaitEvent(s1, eFork, 0);
    cudaStreamWaitEvent(s2, eFork, 0);

    // ---- s1: weight prep + exps passthrough (all overlapped with GEMMs) ----
    transpose_h<<<dim3(13, 16), tb, 0, s1>>>(W1, hw1, 400, 512);
    cudaEventRecord(eW1, s1);
    transpose_h<<<dim3(16, 32), tb, 0, s1>>>(W2, hw2, 512, 1024);
    cudaEventRecord(eW2, s1);
    transpose_h<<<dim3(32, 128), tb, 0, s1>>>(Wl, hwlr, 1024, 4096);
    transpose_h<<<dim3(32, 128), tb, 0, s1>>>(Wr, hwlr + (size_t)4096 * 1024, 1024, 4096);
    copy_f4<<<4, 256, 0, s1>>>((const float4*)bl, (float4*)bcat, 1024);
    copy_f4<<<4, 256, 0, s1>>>((const float4*)br, (float4*)(bcat + 4096), 1024);
    cudaEventRecord(eWlr, s1);
    copy_f4<<<(Nx * 115 + 255) / 256, 256, 0, s1>>>((const float4*)exps,
                                                    (float4*)((float*)d_out + (size_t)N * 460),
                                                    Nx * 115);
    transpose_h<<<dim3(32, 15), tb, 0, s1>>>(Wfc, hwfc, 1024, 460);
    cudaEventRecord(eWfc, s1);

    // ---- s2: graph structure only (gates gat_fused) ----
    zero_int2<<<(N + 255) / 256, 256, 0, s2>>>(deg, cur, N);
    build_edges<<<(ET + 255) / 256, 256, 0, s2>>>(ei, src, dst, deg, E, N);
    scan_excl<<<1, 1024, 0, s2>>>(deg, off, N);
    fill_csr<<<(ET + 255) / 256, 256, 0, s2>>>(dst, off, cur, csr, ET);
    cudaEventRecord(eGraph, s2);

    // ---- s0: main chain ----
    f2h<<<(Nx * 200 + 255) / 256, 256, 0, s0>>>((const float2*)x, (__half2*)hxin, Nx * 200);
    f2h<<<(Nc * 512 + 255) / 256, 256, 0, s0>>>((const float2*)emb, (__half2*)hxc, Nc * 512);

    cudaStreamWaitEvent(s0, eW1, 0);
    gemm_h<true, true><<<gemm_grid(Nx, 512), 256, H_SMEM, s0>>>(hxin, hw1, b1, hxh, Nx, 512, 400);

    cudaStreamWaitEvent(s0, eW2, 0);
    gemm_h<false, true><<<gemm_grid(Nx, 1024), 256, H_SMEM, s0>>>(hxh, hw2, b2, hxc + (size_t)Nc * 1024, Nx, 1024, 512);

    cudaStreamWaitEvent(s0, eWlr, 0);
    gemm_h<false, true><<<gemm_grid(N, 8192), 256, H_SMEM, s0>>>(hxc, hwlr, bcat, hxlr, N, 8192, 1024);

    cudaStreamWaitEvent(s0, eGraph, 0);
    gat_fused<<<N, 256, 0, s0>>>(hxlr, off, csr, src, att, gb, alpha, houtm, N);

    cudaStreamWaitEvent(s0, eWfc, 0);
    gemm_h<false, false><<<gemm_grid(N, 460), 256, H_SMEM, s0>>>(houtm, hwfc, bfc, (float*)d_out, N, 460, 1024);

    // forks joined into s0 via eWfc (covers all of s1) and eGraph (all of s2)
    cudaEventDestroy(eFork);
    cudaEventDestroy(eW1);
    cudaEventDestroy(eW2);
    cudaEventDestroy(eWlr);
    cudaEventDestroy(eWfc);
    cudaEventDestroy(eGraph);
    cudaStreamDestroy(s1);
    cudaStreamDestroy(s2);
}

// round 16
// speedup vs baseline: 1.0288x; 1.0267x over previous
#include <cuda_runtime.h>
#include <cuda_fp16.h>
#include <cstdint>

#define N_HEADS 4
#define NSLOPE 0.2f

#define MAXNX 9000
#define MAXNC 1000
#define MAXN  (MAXNX + MAXNC)
#define MAXE0 40000
#define MAXE  (MAXE0 + MAXN)

// ------------------------- static scratch (no allocs) -------------------------
__device__ __half g_hxin[MAXNX * 400];
__device__ __half g_hxh[MAXNX * 512];
__device__ __half g_hxc[MAXN * 1024];
__device__ __half g_hxlr[(size_t)MAXN * 8192];   // [n, 0:4096)=xl, [4096:8192)=xr
__device__ __half g_houtm[MAXN * 1024];
__device__ __half g_hw1[512 * 400];
__device__ __half g_hw2[1024 * 512];
__device__ __half g_hwlr[(size_t)8192 * 1024];   // Wl^T rows 0-4095, Wr^T rows 4096-8191
__device__ __half g_hwfc[460 * 1024];
__device__ float  g_bcat[8192];
__device__ float  g_alpha[MAXE * N_HEADS];
__device__ int    g_src[MAXE];
__device__ int    g_dst[MAXE];
__device__ int    g_deg[MAXN];
__device__ int    g_off[MAXN + 1];
__device__ int    g_cur[MAXN];
__device__ int    g_csr[MAXE];

// ------------------------- helpers -------------------------
__device__ __forceinline__ void cp16(uint32_t saddr, const void* g, bool valid) {
    int sz = valid ? 16 : 0;   // sz=0 -> 16B zero-fill
    asm volatile("cp.async.cg.shared.global [%0], [%1], 16, %2;\n"
                 :: "r"(saddr), "l"(g), "r"(sz));
}

// ------------------------- small utility kernels -------------------------
__global__ void zero_int2(int* a, int* b, int n) {
    int i = blockIdx.x * blockDim.x + threadIdx.x;
    if (i < n) { a[i] = 0; b[i] = 0; }
}
__global__ void copy_f4(const float4* __restrict__ s, float4* __restrict__ d, int n4) {
    int i = blockIdx.x * blockDim.x + threadIdx.x;
    if (i < n4) d[i] = s[i];
}
__global__ void f2h(const float2* __restrict__ a, __half2* __restrict__ b, int n2) {
    int i = blockIdx.x * blockDim.x + threadIdx.x;
    if (i < n2) b[i] = __float22half2_rn(a[i]);
}
// W [K,N] fp32 row-major -> out [N,K] half (K-major rows)
__global__ void transpose_h(const float* __restrict__ in, __half* __restrict__ out,
                            int K, int N) {
    __shared__ float t[32][33];
    int k0 = blockIdx.x * 32, n0 = blockIdx.y * 32;
    int x = threadIdx.x, y = threadIdx.y;
    #pragma unroll
    for (int j = 0; j < 32; j += 8) {
        int k = k0 + y + j, n = n0 + x;
        t[y + j][x] = (k < K && n < N) ? in[(size_t)k * N + n] : 0.0f;
    }
    __syncthreads();
    #pragma unroll
    for (int j = 0; j < 32; j += 8) {
        int n = n0 + y + j, k = k0 + x;
        if (n < N && k < K) out[(size_t)n * K + k] = __float2half(t[x][y + j]);
    }
}

// edge_index is int32 (JAX x64-disabled downcast)
__global__ void build_edges(const int* __restrict__ ei, int* __restrict__ src,
                            int* __restrict__ dst, int* __restrict__ deg, int E, int N) {
    int e = blockIdx.x * blockDim.x + threadIdx.x;
    int ET = E + N;
    if (e >= ET) return;
    int s, d;
    if (e < E) { s = ei[2 * e]; d = ei[2 * e + 1]; }
    else       { s = d = e - E; }
    src[e] = s; dst[e] = d;
    atomicAdd(&deg[d], 1);
}
__global__ void scan_excl(const int* __restrict__ deg, int* __restrict__ off, int n) {
    __shared__ int sh[1024];
    __shared__ int carry;
    if (threadIdx.x == 0) carry = 0;
    __syncthreads();
    for (int base = 0; base < n; base += 1024) {
        int i = base + threadIdx.x;
        int v = (i < n) ? deg[i] : 0;
        sh[threadIdx.x] = v;
        __syncthreads();
        #pragma unroll
        for (int ofs = 1; ofs < 1024; ofs <<= 1) {
            int t = (threadIdx.x >= ofs) ? sh[threadIdx.x - ofs] : 0;
            __syncthreads();
            sh[threadIdx.x] += t;
            __syncthreads();
        }
        if (i < n) off[i] = carry + sh[threadIdx.x] - v;
        __syncthreads();
        if (threadIdx.x == 1023) carry += sh[1023];
        __syncthreads();
    }
    if (threadIdx.x == 0) off[n] = carry;
}
__global__ void fill_csr(const int* __restrict__ dst, const int* __restrict__ off,
                         int* __restrict__ cur, int* __restrict__ csr, int ET) {
    int e = blockIdx.x * blockDim.x + threadIdx.x;
    if (e >= ET) return;
    int d = dst[e];
    int p = off[d] + atomicAdd(&cur[d], 1);
    csr[p] = e;
}

// ===================== fp16 tensor-core GEMM (m16n8k16 + ldmatrix) =====================
#define BM 128
#define BN 128
#define HBK 64
#define HPAD 72
#define HA_HALVES (BM * HPAD)
#define HB_HALVES (BN * HPAD)
#define HSTG_BYTES ((HA_HALVES + HB_HALVES) * 2)
#define HNST 3
#define H_SMEM (HNST * HSTG_BYTES)

__device__ __forceinline__ void ldm_x4(uint32_t* d, uint32_t addr) {
    asm volatile("ldmatrix.sync.aligned.m8n8.x4.shared.b16 {%0,%1,%2,%3}, [%4];"
                 : "=r"(d[0]), "=r"(d[1]), "=r"(d[2]), "=r"(d[3]) : "r"(addr));
}
__device__ __forceinline__ void mma16816(float* c, const uint32_t* a, uint32_t b0, uint32_t b1) {
    asm volatile(
        "mma.sync.aligned.m16n8k16.row.col.f32.f16.f16.f32 "
        "{%0,%1,%2,%3}, {%4,%5,%6,%7}, {%8,%9}, {%0,%1,%2,%3};\n"
        : "+f"(c[0]), "+f"(c[1]), "+f"(c[2]), "+f"(c[3])
        : "r"(a[0]), "r"(a[1]), "r"(a[2]), "r"(a[3]), "r"(b0), "r"(b1));
}

template <bool RELU, bool HALF_OUT>
__global__ __launch_bounds__(256, 2)
void gemm_h(const __half* __restrict__ A, const __half* __restrict__ Bt,
            const float* __restrict__ bias, void* __restrict__ Cv,
            int M, int N, int K) {
    extern __shared__ char sm[];
    int tid  = threadIdx.x;
    int warp = tid >> 5;
    int lane = tid & 31;
    int g = lane >> 2;
    int t = lane & 3;
    int wm = warp >> 2;
    int wn = warp & 3;
    int mbase = wm * 64;
    int nbase = wn * 32;
    int am0 = blockIdx.y * BM;
    int bn0 = blockIdx.x * BN;
    int NIT = (K + HBK - 1) / HBK;

    float acc[4][4][4];
    #pragma unroll
    for (int i = 0; i < 4; i++)
        #pragma unroll
        for (int j = 0; j < 4; j++)
            #pragma unroll
            for (int k = 0; k < 4; k++) acc[i][j][k] = 0.0f;

    uint32_t smbase = (uint32_t)__cvta_generic_to_shared(sm);

    auto load_stage = [&](int it, int st) {
        int kt = it * HBK;
        uint32_t ab = smbase + (uint32_t)(st * HSTG_BYTES);
        uint32_t bb = ab + HA_HALVES * 2;
        #pragma unroll
        for (int i = 0; i < 4; i++) {
            int idx = tid + i * 256;
            int r = idx >> 3, c = idx & 7;
            int kc = kt + c * 8;
            bool v = (am0 + r < M) && (kc + 8 <= K);
            const __half* gp = A + (size_t)(v ? (am0 + r) : 0) * K + (v ? kc : 0);
            cp16(ab + (uint32_t)(r * 144 + c * 16), gp, v);
        }
        #pragma unroll
        for (int i = 0; i < 4; i++) {
            int idx = tid + i * 256;
            int r = idx >> 3, c = idx & 7;
            int kc = kt + c * 8;
            bool v = (bn0 + r < N) && (kc + 8 <= K);
            const __half* gp = Bt + (size_t)(v ? (bn0 + r) : 0) * K + (v ? kc : 0);
            cp16(bb + (uint32_t)(r * 144 + c * 16), gp, v);
        }
        asm volatile("cp.async.commit_group;\n");
    };

    int a_row = lane & 15;
    int a_k   = (lane & 16) >> 1;
    int b_row = (lane & 7) | ((lane & 16) >> 1);
    int b_k   = lane & 8;

    load_stage(0, 0);
    if (NIT > 1) load_stage(1, 1);

    for (int it = 0; it < NIT; it++) {
        asm volatile("cp.async.wait_group 1;\n");
        __syncthreads();
        if (it + 2 < NIT) load_stage(it + 2, (it + 2) % HNST);

        uint32_t ab = smbase + (uint32_t)((it % HNST) * HSTG_BYTES);
        uint32_t bb = ab + HA_HALVES * 2;

        #pragma unroll
        for (int kk = 0; kk < HBK; kk += 16) {
            uint32_t a[4][4], b[2][4];
            #pragma unroll
            for (int mf = 0; mf < 4; mf++)
                ldm_x4(a[mf], ab + (uint32_t)((mbase + mf * 16 + a_row) * 144 + (kk + a_k) * 2));
            #pragma unroll
            for (int p = 0; p < 2; p++)
                ldm_x4(b[p], bb + (uint32_t)((nbase + p * 16 + b_row) * 144 + (kk + b_k) * 2));
            #pragma unroll
            for (int p = 0; p < 2; p++)
                #pragma unroll
                for (int mf = 0; mf < 4; mf++) {
                    mma16816(acc[mf][2 * p],     a[mf], b[p][0], b[p][1]);
                    mma16816(acc[mf][2 * p + 1], a[mf], b[p][2], b[p][3]);
                }
        }
        __syncthreads();
    }

    #pragma unroll
    for (int mf = 0; mf < 4; mf++) {
        int row0 = am0 + mbase + mf * 16 + g;
        int row1 = row0 + 8;
        #pragma unroll
        for (int nf = 0; nf < 4; nf++) {
            int col = bn0 + nbase + nf * 8 + 2 * t;
            if (col >= N) continue;
            float2 bv = *(const float2*)(bias + col);
            float v0 = acc[mf][nf][0] + bv.x;
            float v1 = acc[mf][nf][1] + bv.y;
            float v2 = acc[mf][nf][2] + bv.x;
            float v3 = acc[mf][nf][3] + bv.y;
            if (RELU) {
                v0 = fmaxf(v0, 0.f); v1 = fmaxf(v1, 0.f);
                v2 = fmaxf(v2, 0.f); v3 = fmaxf(v3, 0.f);
            }
            if (HALF_OUT) {
                __half2* C = (__half2*)Cv;
                if (row0 < M) C[((size_t)row0 * N + col) >> 1] = __floats2half2_rn(v0, v1);
                if (row1 < M) C[((size_t)row1 * N + col) >> 1] = __floats2half2_rn(v2, v3);
            } else {
                float* C = (float*)Cv;
                if (row0 < M) *(float2*)(C + (size_t)row0 * N + col) = make_float2(v0, v1);
                if (row1 < M) *(float2*)(C + (size_t)row1 * N + col) = make_float2(v2, v3);
            }
        }
    }
}

// ------------------------- fused GATv2 (scalar, R13-proven) -------------------------
// xlr rows: [xl | xr], stride 8192 halves.
__global__ __launch_bounds__(256)
void gat_fused(const __half* __restrict__ xlr,
               const int* __restrict__ off, const int* __restrict__ csr,
               const int* __restrict__ src, const float* __restrict__ att,
               const float* __restrict__ gat_bias, float* __restrict__ alpha_s,
               __half* __restrict__ outm, int N) {
    int n = blockIdx.x;
    if (n >= N) return;
    int t = threadIdx.x;
    int lane = t & 31, wid = t >> 5;
    int b = off[n], e2 = off[n + 1];

    __shared__ float s_xr[4096];
    __shared__ float s_att[4096];
    __shared__ float sm_m[N_HEADS], sm_inv[N_HEADS];

    const __half2* xrp = (const __half2*)(xlr + (size_t)n * 8192 + 4096);
    #pragma unroll
    for (int j = 0; j < 8; j++) {
        int idx = t + j * 256;
        float2 f = __half22float2(xrp[idx]);
        s_xr[2 * idx] = f.x; s_xr[2 * idx + 1] = f.y;
    }
    const float4* atp = (const float4*)att;
    #pragma unroll
    for (int j = 0; j < 4; j++) {
        int idx = t + j * 256;
        ((float4*)s_att)[idx] = atp[idx];
    }
    __syncthreads();

    for (int i = b + wid; i < e2; i += 8) {
        int s = src[csr[i]];
        const __half* pl = xlr + (size_t)s * 8192;
        float part[N_HEADS];
        #pragma unroll
        for (int h = 0; h < N_HEADS; h++) {
            float p = 0.0f;
            int base = h * 1024;
            #pragma unroll 8
            for (int k = 0; k < 32; k++) {
                int c = base + lane + k * 32;
                float v = __half2float(pl[c]) + s_xr[c];
                v = (v > 0.0f) ? v : NSLOPE * v;
                p += v * s_att[c];
            }
            part[h] = p;
        }
        #pragma unroll
        for (int h = 0; h < N_HEADS; h++) {
            float v = part[h];
            #pragma unroll
            for (int o = 16; o; o >>= 1) v += __shfl_xor_sync(0xffffffffu, v, o);
            if (lane == 0) alpha_s[(size_t)i * N_HEADS + h] = v;
        }
    }
    __syncthreads();

    if (t < N_HEADS) {
        float m = -1e30f;
        for (int i = b; i < e2; i++)
            m = fmaxf(m, alpha_s[(size_t)i * N_HEADS + t]);
        float z = 0.0f;
        for (int i = b; i < e2; i++)
            z += __expf(alpha_s[(size_t)i * N_HEADS + t] - m);
        sm_m[t] = m;
        sm_inv[t] = 1.0f / (z + 1e-16f);
    }
    __syncthreads();
    float mf0 = sm_m[0], mf1 = sm_m[1], mf2 = sm_m[2], mf3 = sm_m[3];
    float iv0 = sm_inv[0], iv1 = sm_inv[1], iv2 = sm_inv[2], iv3 = sm_inv[3];

    float acc[16];
    #pragma unroll
    for (int j = 0; j < 16; j++) acc[j] = 0.0f;

    for (int i = b; i < e2; i++) {
        int s = src[csr[i]];
        const __half* pl = xlr + (size_t)s * 8192;
        const float* ap = alpha_s + (size_t)i * N_HEADS;
        float w0 = __expf(ap[0] - mf0) * iv0;
        float w1 = __expf(ap[1] - mf1) * iv1;
        float w2 = __expf(ap[2] - mf2) * iv2;
        float w3 = __expf(ap[3] - mf3) * iv3;
        #pragma unroll
        for (int j = 0; j < 4; j++) {
            int c = t + j * 256;
            acc[j]      += w0 * __half2float(pl[c]);
            acc[j + 4]  += w1 * __half2float(pl[1024 + c]);
            acc[j + 8]  += w2 * __half2float(pl[2048 + c]);
            acc[j + 12] += w3 * __half2float(pl[3072 + c]);
        }
    }

    #pragma unroll
    for (int jc = 0; jc < 4; jc++) {
        int c = t + jc * 256;
        float v = 0.25f * (acc[jc] + acc[jc + 4] + acc[jc + 8] + acc[jc + 12]);
        outm[(size_t)n * 1024 + c] = __float2half(v + gat_bias[c]);
    }
}

// ------------------------- host orchestration -------------------------
static inline dim3 gemm_grid(int M, int N) {
    return dim3((N + BN - 1) / BN, (M + BM - 1) / BM);
}

extern "C" void kernel_launch(void* const* d_in, const int* in_sizes, int n_in,
                              void* d_out, int out_size) {
    const float* x    = (const float*)d_in[0];
    const float* emb  = (const float*)d_in[1];
    const int*   ei   = (const int*)d_in[2];
    const float* exps = (const float*)d_in[3];
    const float* W1   = (const float*)d_in[4];
    const float* b1   = (const float*)d_in[5];
    const float* W2   = (const float*)d_in[6];
    const float* b2   = (const float*)d_in[7];
    const float* Wl   = (const float*)d_in[8];
    const float* bl   = (const float*)d_in[9];
    const float* Wr   = (const float*)d_in[10];
    const float* br   = (const float*)d_in[11];
    const float* att  = (const float*)d_in[12];
    const float* gb   = (const float*)d_in[13];
    const float* Wfc  = (const float*)d_in[14];
    const float* bfc  = (const float*)d_in[15];

    int Nx = in_sizes[0] / 400;
    int Nc = in_sizes[1] / 1024;
    int E  = in_sizes[2] / 2;
    int N  = Nx + Nc;
    int ET = E + N;

    __half *hxin, *hxh, *hxc, *hxlr, *houtm, *hw1, *hw2, *hwlr, *hwfc;
    float *alpha, *bcat;
    int *src, *dst, *deg, *off, *cur, *csr;
    cudaGetSymbolAddress((void**)&hxin,  g_hxin);
    cudaGetSymbolAddress((void**)&hxh,   g_hxh);
    cudaGetSymbolAddress((void**)&hxc,   g_hxc);
    cudaGetSymbolAddress((void**)&hxlr,  g_hxlr);
    cudaGetSymbolAddress((void**)&houtm, g_houtm);
    cudaGetSymbolAddress((void**)&hw1,   g_hw1);
    cudaGetSymbolAddress((void**)&hw2,   g_hw2);
    cudaGetSymbolAddress((void**)&hwlr,  g_hwlr);
    cudaGetSymbolAddress((void**)&hwfc,  g_hwfc);
    cudaGetSymbolAddress((void**)&bcat,  g_bcat);
    cudaGetSymbolAddress((void**)&alpha, g_alpha);
    cudaGetSymbolAddress((void**)&src,   g_src);
    cudaGetSymbolAddress((void**)&dst,   g_dst);
    cudaGetSymbolAddress((void**)&deg,   g_deg);
    cudaGetSymbolAddress((void**)&off,   g_off);
    cudaGetSymbolAddress((void**)&cur,   g_cur);
    cudaGetSymbolAddress((void**)&csr,   g_csr);

    cudaFuncSetAttribute(gemm_h<true,  true >, cudaFuncAttributeMaxDynamicSharedMemorySize, H_SMEM);
    cudaFuncSetAttribute(gemm_h<false, true >, cudaFuncAttributeMaxDynamicSharedMemorySize, H_SMEM);
    cudaFuncSetAttribute(gemm_h<false, false>, cudaFuncAttributeMaxDynamicSharedMemorySize, H_SMEM);

    dim3 tb(32, 8);
    cudaStream_t s0 = 0, s1, s2;
    cudaStreamCreate(&s1);
    cudaStreamCreate(&s2);
    cudaEvent_t eFork, eW1, eW2, eWlr, eWfc, eGraph, eEmb, eCproj;
    cudaEventCreateWithFlags(&eFork,  cudaEventDisableTiming);
    cudaEventCreateWithFlags(&eW1,    cudaEventDisableTiming);
    cudaEventCreateWithFlags(&eW2,    cudaEventDisableTiming);
    cudaEventCreateWithFlags(&eWlr,   cudaEventDisableTiming);
    cudaEventCreateWithFlags(&eWfc,   cudaEventDisableTiming);
    cudaEventCreateWithFlags(&eGraph, cudaEventDisableTiming);
    cudaEventCreateWithFlags(&eEmb,   cudaEventDisableTiming);
    cudaEventCreateWithFlags(&eCproj, cudaEventDisableTiming);

    // ---- fork side streams ----
    cudaEventRecord(eFork, s0);
    cudaStreamWaitEvent(s1, eFork, 0);
    cudaStreamWaitEvent(s2, eFork, 0);

    // ---- s0: input conversions first (eEmb gates the centroid projection) ----
    f2h<<<(Nc * 512 + 255) / 256, 256, 0, s0>>>((const float2*)emb, (__half2*)hxc, Nc * 512);
    cudaEventRecord(eEmb, s0);
    f2h<<<(Nx * 200 + 255) / 256, 256, 0, s0>>>((const float2*)x, (__half2*)hxin, Nx * 200);

    // ---- s1: weight prep + centroid projection + exps (all overlapped) ----
    transpose_h<<<dim3(13, 16), tb, 0, s1>>>(W1, hw1, 400, 512);
    cudaEventRecord(eW1, s1);
    transpose_h<<<dim3(16, 32), tb, 0, s1>>>(W2, hw2, 512, 1024);
    cudaEventRecord(eW2, s1);
    transpose_h<<<dim3(32, 128), tb, 0, s1>>>(Wl, hwlr, 1024, 4096);
    transpose_h<<<dim3(32, 128), tb, 0, s1>>>(Wr, hwlr + (size_t)4096 * 1024, 1024, 4096);
    copy_f4<<<4, 256, 0, s1>>>((const float4*)bl, (float4*)bcat, 1024);
    copy_f4<<<4, 256, 0, s1>>>((const float4*)br, (float4*)(bcat + 4096), 1024);
    cudaEventRecord(eWlr, s1);
    // centroid rows projection (M=Nc), overlaps the MLP GEMMs on s0
    cudaStreamWaitEvent(s1, eEmb, 0);
    gemm_h<false, true><<<gemm_grid(Nc, 8192), 256, H_SMEM, s1>>>(hxc, hwlr, bcat, hxlr, Nc, 8192, 1024);
    cudaEventRecord(eCproj, s1);
    copy_f4<<<(Nx * 115 + 255) / 256, 256, 0, s1>>>((const float4*)exps,
                                                    (float4*)((float*)d_out + (size_t)N * 460),
                                                    Nx * 115);
    transpose_h<<<dim3(32, 15), tb, 0, s1>>>(Wfc, hwfc, 1024, 460);
    cudaEventRecord(eWfc, s1);

    // ---- s2: graph structure only (gates gat_fused) ----
    zero_int2<<<(N + 255) / 256, 256, 0, s2>>>(deg, cur, N);
    build_edges<<<(ET + 255) / 256, 256, 0, s2>>>(ei, src, dst, deg, E, N);
    scan_excl<<<1, 1024, 0, s2>>>(deg, off, N);
    fill_csr<<<(ET + 255) / 256, 256, 0, s2>>>(dst, off, cur, csr, ET);
    cudaEventRecord(eGraph, s2);

    // ---- s0: main chain ----
    cudaStreamWaitEvent(s0, eW1, 0);
    gemm_h<true, true><<<gemm_grid(Nx, 512), 256, H_SMEM, s0>>>(hxin, hw1, b1, hxh, Nx, 512, 400);

    cudaStreamWaitEvent(s0, eW2, 0);
    gemm_h<false, true><<<gemm_grid(Nx, 1024), 256, H_SMEM, s0>>>(hxh, hw2, b2, hxc + (size_t)Nc * 1024, Nx, 1024, 512);

    cudaStreamWaitEvent(s0, eWlr, 0);
    // node rows projection (M=Nx), output offset past centroid rows
    gemm_h<false, true><<<gemm_grid(Nx, 8192), 256, H_SMEM, s0>>>(hxc + (size_t)Nc * 1024, hwlr, bcat,
                                                                  hxlr + (size_t)Nc * 8192, Nx, 8192, 1024);

    cudaStreamWaitEvent(s0, eGraph, 0);
    cudaStreamWaitEvent(s0, eCproj, 0);
    gat_fused<<<N, 256, 0, s0>>>(hxlr, off, csr, src, att, gb, alpha, houtm, N);

    cudaStreamWaitEvent(s0, eWfc, 0);
    gemm_h<false, false><<<gemm_grid(N, 460), 256, H_SMEM, s0>>>(houtm, hwfc, bfc, (float*)d_out, N, 460, 1024);

    // forks joined into s0 via eWfc (covers all of s1) and eGraph (all of s2)
    cudaEventDestroy(eFork);
    cudaEventDestroy(eW1);
    cudaEventDestroy(eW2);
    cudaEventDestroy(eWlr);
    cudaEventDestroy(eWfc);
    cudaEventDestroy(eGraph);
    cudaEventDestroy(eEmb);
    cudaEventDestroy(eCproj);
    cudaStreamDestroy(s1);
    cudaStreamDestroy(s2);
}

// round 17
// speedup vs baseline: 1.0358x; 1.0068x over previous
#include <cuda_runtime.h>
#include <cuda_fp16.h>
#include <cstdint>

#define N_HEADS 4
#define NSLOPE 0.2f

#define MAXNX 9000
#define MAXNC 1000
#define MAXN  (MAXNX + MAXNC)
#define MAXE0 40000
#define MAXE  (MAXE0 + MAXN)

// ------------------------- static scratch (no allocs) -------------------------
__device__ __half g_hxin[MAXNX * 400];
__device__ __half g_hxh[MAXNX * 512];
__device__ __half g_hxc[MAXN * 1024];
__device__ __half g_hxlr[(size_t)MAXN * 8192];   // [n, 0:4096)=xl, [4096:8192)=xr
__device__ __half g_houtm[MAXN * 1024];
__device__ __half g_hw1[512 * 400];
__device__ __half g_hw2[1024 * 512];
__device__ __half g_hwlr[(size_t)8192 * 1024];   // Wl^T rows 0-4095, Wr^T rows 4096-8191
__device__ __half g_hwfc[460 * 1024];
__device__ float  g_bcat[8192];
__device__ float  g_alpha[MAXE * N_HEADS];
__device__ int    g_src[MAXE];
__device__ int    g_dst[MAXE];
__device__ int    g_deg[MAXN];
__device__ int    g_off[MAXN + 1];
__device__ int    g_cur[MAXN];
__device__ int    g_csr[MAXE];

// ------------------------- helpers -------------------------
__device__ __forceinline__ void cp16(uint32_t saddr, const void* g, bool valid) {
    int sz = valid ? 16 : 0;   // sz=0 -> 16B zero-fill
    asm volatile("cp.async.cg.shared.global [%0], [%1], 16, %2;\n"
                 :: "r"(saddr), "l"(g), "r"(sz));
}

// ------------------------- small utility kernels -------------------------
__global__ void zero_int2(int* a, int* b, int n) {
    int i = blockIdx.x * blockDim.x + threadIdx.x;
    if (i < n) { a[i] = 0; b[i] = 0; }
}
__global__ void copy_f4(const float4* __restrict__ s, float4* __restrict__ d, int n4) {
    int i = blockIdx.x * blockDim.x + threadIdx.x;
    if (i < n4) d[i] = s[i];
}
__global__ void f2h(const float2* __restrict__ a, __half2* __restrict__ b, int n2) {
    int i = blockIdx.x * blockDim.x + threadIdx.x;
    if (i < n2) b[i] = __float22half2_rn(a[i]);
}
// W [K,N] fp32 row-major -> out [N,K] half (K-major rows)
__global__ void transpose_h(const float* __restrict__ in, __half* __restrict__ out,
                            int K, int N) {
    __shared__ float t[32][33];
    int k0 = blockIdx.x * 32, n0 = blockIdx.y * 32;
    int x = threadIdx.x, y = threadIdx.y;
    #pragma unroll
    for (int j = 0; j < 32; j += 8) {
        int k = k0 + y + j, n = n0 + x;
        t[y + j][x] = (k < K && n < N) ? in[(size_t)k * N + n] : 0.0f;
    }
    __syncthreads();
    #pragma unroll
    for (int j = 0; j < 32; j += 8) {
        int n = n0 + y + j, k = k0 + x;
        if (n < N && k < K) out[(size_t)n * K + k] = __float2half(t[x][y + j]);
    }
}

// edge_index is int32 (JAX x64-disabled downcast)
__global__ void build_edges(const int* __restrict__ ei, int* __restrict__ src,
                            int* __restrict__ dst, int* __restrict__ deg, int E, int N) {
    int e = blockIdx.x * blockDim.x + threadIdx.x;
    int ET = E + N;
    if (e >= ET) return;
    int s, d;
    if (e < E) { s = ei[2 * e]; d = ei[2 * e + 1]; }
    else       { s = d = e - E; }
    src[e] = s; dst[e] = d;
    atomicAdd(&deg[d], 1);
}
__global__ void scan_excl(const int* __restrict__ deg, int* __restrict__ off, int n) {
    __shared__ int sh[1024];
    __shared__ int carry;
    if (threadIdx.x == 0) carry = 0;
    __syncthreads();
    for (int base = 0; base < n; base += 1024) {
        int i = base + threadIdx.x;
        int v = (i < n) ? deg[i] : 0;
        sh[threadIdx.x] = v;
        __syncthreads();
        #pragma unroll
        for (int ofs = 1; ofs < 1024; ofs <<= 1) {
            int t = (threadIdx.x >= ofs) ? sh[threadIdx.x - ofs] : 0;
            __syncthreads();
            sh[threadIdx.x] += t;
            __syncthreads();
        }
        if (i < n) off[i] = carry + sh[threadIdx.x] - v;
        __syncthreads();
        if (threadIdx.x == 1023) carry += sh[1023];
        __syncthreads();
    }
    if (threadIdx.x == 0) off[n] = carry;
}
__global__ void fill_csr(const int* __restrict__ dst, const int* __restrict__ off,
                         int* __restrict__ cur, int* __restrict__ csr, int ET) {
    int e = blockIdx.x * blockDim.x + threadIdx.x;
    if (e >= ET) return;
    int d = dst[e];
    int p = off[d] + atomicAdd(&cur[d], 1);
    csr[p] = e;
}

// ===================== fp16 tensor-core GEMM (m16n8k16 + ldmatrix) =====================
// Single barrier per mainloop iteration: the top wait_group+__syncthreads of
// iteration it+1 already guarantees all warps finished reading stage it%3
// before anyone writes stage (it+3)%3 == it%3.
#define BM 128
#define BN 128
#define HBK 64
#define HPAD 72
#define HA_HALVES (BM * HPAD)
#define HB_HALVES (BN * HPAD)
#define HSTG_BYTES ((HA_HALVES + HB_HALVES) * 2)
#define HNST 3
#define H_SMEM (HNST * HSTG_BYTES)

__device__ __forceinline__ void ldm_x4(uint32_t* d, uint32_t addr) {
    asm volatile("ldmatrix.sync.aligned.m8n8.x4.shared.b16 {%0,%1,%2,%3}, [%4];"
                 : "=r"(d[0]), "=r"(d[1]), "=r"(d[2]), "=r"(d[3]) : "r"(addr));
}
__device__ __forceinline__ void mma16816(float* c, const uint32_t* a, uint32_t b0, uint32_t b1) {
    asm volatile(
        "mma.sync.aligned.m16n8k16.row.col.f32.f16.f16.f32 "
        "{%0,%1,%2,%3}, {%4,%5,%6,%7}, {%8,%9}, {%0,%1,%2,%3};\n"
        : "+f"(c[0]), "+f"(c[1]), "+f"(c[2]), "+f"(c[3])
        : "r"(a[0]), "r"(a[1]), "r"(a[2]), "r"(a[3]), "r"(b0), "r"(b1));
}

template <bool RELU, bool HALF_OUT>
__global__ __launch_bounds__(256, 2)
void gemm_h(const __half* __restrict__ A, const __half* __restrict__ Bt,
            const float* __restrict__ bias, void* __restrict__ Cv,
            int M, int N, int K) {
    extern __shared__ char sm[];
    int tid  = threadIdx.x;
    int warp = tid >> 5;
    int lane = tid & 31;
    int g = lane >> 2;
    int t = lane & 3;
    int wm = warp >> 2;
    int wn = warp & 3;
    int mbase = wm * 64;
    int nbase = wn * 32;
    int am0 = blockIdx.y * BM;
    int bn0 = blockIdx.x * BN;
    int NIT = (K + HBK - 1) / HBK;

    float acc[4][4][4];
    #pragma unroll
    for (int i = 0; i < 4; i++)
        #pragma unroll
        for (int j = 0; j < 4; j++)
            #pragma unroll
            for (int k = 0; k < 4; k++) acc[i][j][k] = 0.0f;

    uint32_t smbase = (uint32_t)__cvta_generic_to_shared(sm);

    auto load_stage = [&](int it, int st) {
        int kt = it * HBK;
        uint32_t ab = smbase + (uint32_t)(st * HSTG_BYTES);
        uint32_t bb = ab + HA_HALVES * 2;
        #pragma unroll
        for (int i = 0; i < 4; i++) {
            int idx = tid + i * 256;
            int r = idx >> 3, c = idx & 7;
            int kc = kt + c * 8;
            bool v = (am0 + r < M) && (kc + 8 <= K);
            const __half* gp = A + (size_t)(v ? (am0 + r) : 0) * K + (v ? kc : 0);
            cp16(ab + (uint32_t)(r * 144 + c * 16), gp, v);
        }
        #pragma unroll
        for (int i = 0; i < 4; i++) {
            int idx = tid + i * 256;
            int r = idx >> 3, c = idx & 7;
            int kc = kt + c * 8;
            bool v = (bn0 + r < N) && (kc + 8 <= K);
            const __half* gp = Bt + (size_t)(v ? (bn0 + r) : 0) * K + (v ? kc : 0);
            cp16(bb + (uint32_t)(r * 144 + c * 16), gp, v);
        }
        asm volatile("cp.async.commit_group;\n");
    };

    int a_row = lane & 15;
    int a_k   = (lane & 16) >> 1;
    int b_row = (lane & 7) | ((lane & 16) >> 1);
    int b_k   = lane & 8;

    load_stage(0, 0);
    if (NIT > 1) load_stage(1, 1);

    for (int it = 0; it < NIT; it++) {
        asm volatile("cp.async.wait_group 1;\n");
        __syncthreads();
        if (it + 2 < NIT) load_stage(it + 2, (it + 2) % HNST);

        uint32_t ab = smbase + (uint32_t)((it % HNST) * HSTG_BYTES);
        uint32_t bb = ab + HA_HALVES * 2;

        #pragma unroll
        for (int kk = 0; kk < HBK; kk += 16) {
            uint32_t a[4][4], b[2][4];
            #pragma unroll
            for (int mf = 0; mf < 4; mf++)
                ldm_x4(a[mf], ab + (uint32_t)((mbase + mf * 16 + a_row) * 144 + (kk + a_k) * 2));
            #pragma unroll
            for (int p = 0; p < 2; p++)
                ldm_x4(b[p], bb + (uint32_t)((nbase + p * 16 + b_row) * 144 + (kk + b_k) * 2));
            #pragma unroll
            for (int p = 0; p < 2; p++)
                #pragma unroll
                for (int mf = 0; mf < 4; mf++) {
                    mma16816(acc[mf][2 * p],     a[mf], b[p][0], b[p][1]);
                    mma16816(acc[mf][2 * p + 1], a[mf], b[p][2], b[p][3]);
                }
        }
        // no trailing __syncthreads: WAR safety is provided by the next
        // iteration's wait_group + __syncthreads before any smem write.
    }

    #pragma unroll
    for (int mf = 0; mf < 4; mf++) {
        int row0 = am0 + mbase + mf * 16 + g;
        int row1 = row0 + 8;
        #pragma unroll
        for (int nf = 0; nf < 4; nf++) {
            int col = bn0 + nbase + nf * 8 + 2 * t;
            if (col >= N) continue;
            float2 bv = *(const float2*)(bias + col);
            float v0 = acc[mf][nf][0] + bv.x;
            float v1 = acc[mf][nf][1] + bv.y;
            float v2 = acc[mf][nf][2] + bv.x;
            float v3 = acc[mf][nf][3] + bv.y;
            if (RELU) {
                v0 = fmaxf(v0, 0.f); v1 = fmaxf(v1, 0.f);
                v2 = fmaxf(v2, 0.f); v3 = fmaxf(v3, 0.f);
            }
            if (HALF_OUT) {
                __half2* C = (__half2*)Cv;
                if (row0 < M) C[((size_t)row0 * N + col) >> 1] = __floats2half2_rn(v0, v1);
                if (row1 < M) C[((size_t)row1 * N + col) >> 1] = __floats2half2_rn(v2, v3);
            } else {
                float* C = (float*)Cv;
                if (row0 < M) *(float2*)(C + (size_t)row0 * N + col) = make_float2(v0, v1);
                if (row1 < M) *(float2*)(C + (size_t)row1 * N + col) = make_float2(v2, v3);
            }
        }
    }
}

// ------------------------- fused GATv2 (scalar, R13-proven) -------------------------
__global__ __launch_bounds__(256)
void gat_fused(const __half* __restrict__ xlr,
               const int* __restrict__ off, const int* __restrict__ csr,
               const int* __restrict__ src, const float* __restrict__ att,
               const float* __restrict__ gat_bias, float* __restrict__ alpha_s,
               __half* __restrict__ outm, int N) {
    int n = blockIdx.x;
    if (n >= N) return;
    int t = threadIdx.x;
    int lane = t & 31, wid = t >> 5;
    int b = off[n], e2 = off[n + 1];

    __shared__ float s_xr[4096];
    __shared__ float s_att[4096];
    __shared__ float sm_m[N_HEADS], sm_inv[N_HEADS];

    const __half2* xrp = (const __half2*)(xlr + (size_t)n * 8192 + 4096);
    #pragma unroll
    for (int j = 0; j < 8; j++) {
        int idx = t + j * 256;
        float2 f = __half22float2(xrp[idx]);
        s_xr[2 * idx] = f.x; s_xr[2 * idx + 1] = f.y;
    }
    const float4* atp = (const float4*)att;
    #pragma unroll
    for (int j = 0; j < 4; j++) {
        int idx = t + j * 256;
        ((float4*)s_att)[idx] = atp[idx];
    }
    __syncthreads();

    for (int i = b + wid; i < e2; i += 8) {
        int s = src[csr[i]];
        const __half* pl = xlr + (size_t)s * 8192;
        float part[N_HEADS];
        #pragma unroll
        for (int h = 0; h < N_HEADS; h++) {
            float p = 0.0f;
            int base = h * 1024;
            #pragma unroll 8
            for (int k = 0; k < 32; k++) {
                int c = base + lane + k * 32;
                float v = __half2float(pl[c]) + s_xr[c];
                v = (v > 0.0f) ? v : NSLOPE * v;
                p += v * s_att[c];
            }
            part[h] = p;
        }
        #pragma unroll
        for (int h = 0; h < N_HEADS; h++) {
            float v = part[h];
            #pragma unroll
            for (int o = 16; o; o >>= 1) v += __shfl_xor_sync(0xffffffffu, v, o);
            if (lane == 0) alpha_s[(size_t)i * N_HEADS + h] = v;
        }
    }
    __syncthreads();

    if (t < N_HEADS) {
        float m = -1e30f;
        for (int i = b; i < e2; i++)
            m = fmaxf(m, alpha_s[(size_t)i * N_HEADS + t]);
        float z = 0.0f;
        for (int i = b; i < e2; i++)
            z += __expf(alpha_s[(size_t)i * N_HEADS + t] - m);
        sm_m[t] = m;
        sm_inv[t] = 1.0f / (z + 1e-16f);
    }
    __syncthreads();
    float mf0 = sm_m[0], mf1 = sm_m[1], mf2 = sm_m[2], mf3 = sm_m[3];
    float iv0 = sm_inv[0], iv1 = sm_inv[1], iv2 = sm_inv[2], iv3 = sm_inv[3];

    float acc[16];
    #pragma unroll
    for (int j = 0; j < 16; j++) acc[j] = 0.0f;

    for (int i = b; i < e2; i++) {
        int s = src[csr[i]];
        const __half* pl = xlr + (size_t)s * 8192;
        const float* ap = alpha_s + (size_t)i * N_HEADS;
        float w0 = __expf(ap[0] - mf0) * iv0;
        float w1 = __expf(ap[1] - mf1) * iv1;
        float w2 = __expf(ap[2] - mf2) * iv2;
        float w3 = __expf(ap[3] - mf3) * iv3;
        #pragma unroll
        for (int j = 0; j < 4; j++) {
            int c = t + j * 256;
            acc[j]      += w0 * __half2float(pl[c]);
            acc[j + 4]  += w1 * __half2float(pl[1024 + c]);
            acc[j + 8]  += w2 * __half2float(pl[2048 + c]);
            acc[j + 12] += w3 * __half2float(pl[3072 + c]);
        }
    }

    #pragma unroll
    for (int jc = 0; jc < 4; jc++) {
        int c = t + jc * 256;
        float v = 0.25f * (acc[jc] + acc[jc + 4] + acc[jc + 8] + acc[jc + 12]);
        outm[(size_t)n * 1024 + c] = __float2half(v + gat_bias[c]);
    }
}

// ------------------------- host orchestration -------------------------
static inline dim3 gemm_grid(int M, int N) {
    return dim3((N + BN - 1) / BN, (M + BM - 1) / BM);
}

extern "C" void kernel_launch(void* const* d_in, const int* in_sizes, int n_in,
                              void* d_out, int out_size) {
    const float* x    = (const float*)d_in[0];
    const float* emb  = (const float*)d_in[1];
    const int*   ei   = (const int*)d_in[2];
    const float* exps = (const float*)d_in[3];
    const float* W1   = (const float*)d_in[4];
    const float* b1   = (const float*)d_in[5];
    const float* W2   = (const float*)d_in[6];
    const float* b2   = (const float*)d_in[7];
    const float* Wl   = (const float*)d_in[8];
    const float* bl   = (const float*)d_in[9];
    const float* Wr   = (const float*)d_in[10];
    const float* br   = (const float*)d_in[11];
    const float* att  = (const float*)d_in[12];
    const float* gb   = (const float*)d_in[13];
    const float* Wfc  = (const float*)d_in[14];
    const float* bfc  = (const float*)d_in[15];

    int Nx = in_sizes[0] / 400;
    int Nc = in_sizes[1] / 1024;
    int E  = in_sizes[2] / 2;
    int N  = Nx + Nc;
    int ET = E + N;

    __half *hxin, *hxh, *hxc, *hxlr, *houtm, *hw1, *hw2, *hwlr, *hwfc;
    float *alpha, *bcat;
    int *src, *dst, *deg, *off, *cur, *csr;
    cudaGetSymbolAddress((void**)&hxin,  g_hxin);
    cudaGetSymbolAddress((void**)&hxh,   g_hxh);
    cudaGetSymbolAddress((void**)&hxc,   g_hxc);
    cudaGetSymbolAddress((void**)&hxlr,  g_hxlr);
    cudaGetSymbolAddress((void**)&houtm, g_houtm);
    cudaGetSymbolAddress((void**)&hw1,   g_hw1);
    cudaGetSymbolAddress((void**)&hw2,   g_hw2);
    cudaGetSymbolAddress((void**)&hwlr,  g_hwlr);
    cudaGetSymbolAddress((void**)&hwfc,  g_hwfc);
    cudaGetSymbolAddress((void**)&bcat,  g_bcat);
    cudaGetSymbolAddress((void**)&alpha, g_alpha);
    cudaGetSymbolAddress((void**)&src,   g_src);
    cudaGetSymbolAddress((void**)&dst,   g_dst);
    cudaGetSymbolAddress((void**)&deg,   g_deg);
    cudaGetSymbolAddress((void**)&off,   g_off);
    cudaGetSymbolAddress((void**)&cur,   g_cur);
    cudaGetSymbolAddress((void**)&csr,   g_csr);

    cudaFuncSetAttribute(gemm_h<true,  true >, cudaFuncAttributeMaxDynamicSharedMemorySize, H_SMEM);
    cudaFuncSetAttribute(gemm_h<false, true >, cudaFuncAttributeMaxDynamicSharedMemorySize, H_SMEM);
    cudaFuncSetAttribute(gemm_h<false, false>, cudaFuncAttributeMaxDynamicSharedMemorySize, H_SMEM);

    dim3 tb(32, 8);
    cudaStream_t s0 = 0, s1, s2;
    cudaStreamCreate(&s1);
    cudaStreamCreate(&s2);
    cudaEvent_t eFork, eW1, eW2, eWlr, eWfc, eGraph, eEmb, eCproj;
    cudaEventCreateWithFlags(&eFork,  cudaEventDisableTiming);
    cudaEventCreateWithFlags(&eW1,    cudaEventDisableTiming);
    cudaEventCreateWithFlags(&eW2,    cudaEventDisableTiming);
    cudaEventCreateWithFlags(&eWlr,   cudaEventDisableTiming);
    cudaEventCreateWithFlags(&eWfc,   cudaEventDisableTiming);
    cudaEventCreateWithFlags(&eGraph, cudaEventDisableTiming);
    cudaEventCreateWithFlags(&eEmb,   cudaEventDisableTiming);
    cudaEventCreateWithFlags(&eCproj, cudaEventDisableTiming);

    // ---- fork side streams ----
    cudaEventRecord(eFork, s0);
    cudaStreamWaitEvent(s1, eFork, 0);
    cudaStreamWaitEvent(s2, eFork, 0);

    // ---- s0: input conversions first (eEmb gates the centroid projection) ----
    f2h<<<(Nc * 512 + 255) / 256, 256, 0, s0>>>((const float2*)emb, (__half2*)hxc, Nc * 512);
    cudaEventRecord(eEmb, s0);
    f2h<<<(Nx * 200 + 255) / 256, 256, 0, s0>>>((const float2*)x, (__half2*)hxin, Nx * 200);

    // ---- s1: weight prep + centroid projection + exps (all overlapped) ----
    transpose_h<<<dim3(13, 16), tb, 0, s1>>>(W1, hw1, 400, 512);
    cudaEventRecord(eW1, s1);
    transpose_h<<<dim3(16, 32), tb, 0, s1>>>(W2, hw2, 512, 1024);
    cudaEventRecord(eW2, s1);
    transpose_h<<<dim3(32, 128), tb, 0, s1>>>(Wl, hwlr, 1024, 4096);
    transpose_h<<<dim3(32, 128), tb, 0, s1>>>(Wr, hwlr + (size_t)4096 * 1024, 1024, 4096);
    copy_f4<<<4, 256, 0, s1>>>((const float4*)bl, (float4*)bcat, 1024);
    copy_f4<<<4, 256, 0, s1>>>((const float4*)br, (float4*)(bcat + 4096), 1024);
    cudaEventRecord(eWlr, s1);
    cudaStreamWaitEvent(s1, eEmb, 0);
    gemm_h<false, true><<<gemm_grid(Nc, 8192), 256, H_SMEM, s1>>>(hxc, hwlr, bcat, hxlr, Nc, 8192, 1024);
    cudaEventRecord(eCproj, s1);
    copy_f4<<<(Nx * 115 + 255) / 256, 256, 0, s1>>>((const float4*)exps,
                                                    (float4*)((float*)d_out + (size_t)N * 460),
                                                    Nx * 115);
    transpose_h<<<dim3(32, 15), tb, 0, s1>>>(Wfc, hwfc, 1024, 460);
    cudaEventRecord(eWfc, s1);

    // ---- s2: graph structure only (gates gat_fused) ----
    zero_int2<<<(N + 255) / 256, 256, 0, s2>>>(deg, cur, N);
    build_edges<<<(ET + 255) / 256, 256, 0, s2>>>(ei, src, dst, deg, E, N);
    scan_excl<<<1, 1024, 0, s2>>>(deg, off, N);
    fill_csr<<<(ET + 255) / 256, 256, 0, s2>>>(dst, off, cur, csr, ET);
    cudaEventRecord(eGraph, s2);

    // ---- s0: main chain ----
    cudaStreamWaitEvent(s0, eW1, 0);
    gemm_h<true, true><<<gemm_grid(Nx, 512), 256, H_SMEM, s0>>>(hxin, hw1, b1, hxh, Nx, 512, 400);

    cudaStreamWaitEvent(s0, eW2, 0);
    gemm_h<false, true><<<gemm_grid(Nx, 1024), 256, H_SMEM, s0>>>(hxh, hw2, b2, hxc + (size_t)Nc * 1024, Nx, 1024, 512);

    cudaStreamWaitEvent(s0, eWlr, 0);
    gemm_h<false, true><<<gemm_grid(Nx, 8192), 256, H_SMEM, s0>>>(hxc + (size_t)Nc * 1024, hwlr, bcat,
                                                                  hxlr + (size_t)Nc * 8192, Nx, 8192, 1024);

    cudaStreamWaitEvent(s0, eGraph, 0);
    cudaStreamWaitEvent(s0, eCproj, 0);
    gat_fused<<<N, 256, 0, s0>>>(hxlr, off, csr, src, att, gb, alpha, houtm, N);

    cudaStreamWaitEvent(s0, eWfc, 0);
    gemm_h<false, false><<<gemm_grid(N, 460), 256, H_SMEM, s0>>>(houtm, hwfc, bfc, (float*)d_out, N, 460, 1024);

    // forks joined into s0 via eWfc (covers all of s1) and eGraph (all of s2)
    cudaEventDestroy(eFork);
    cudaEventDestroy(eW1);
    cudaEventDestroy(eW2);
    cudaEventDestroy(eWlr);
    cudaEventDestroy(eWfc);
    cudaEventDestroy(eGraph);
    cudaEventDestroy(eEmb);
    cudaEventDestroy(eCproj);
    cudaStreamDestroy(s1);
    cudaStreamDestroy(s2);
}